// round 1
// baseline (speedup 1.0000x reference)
#include <cuda_runtime.h>
#include <cstdint>
#include <cstddef>

// SSD post-processing, fused: decode + softmax-max + per-batch greedy NMS.
// One block per batch image. B=128, N=8732, C=21, 4+21=25 floats per anchor.

#define NEGV (-1e9f)

constexpr int TPB   = 512;              // threads per block (16 warps)
constexpr int ITEMS = 18;               // ceil(8732 / 512)
constexpr int MAXN  = TPB * ITEMS;      // 9216 slots
constexpr int WARPS = TPB / 32;

__global__ __launch_bounds__(TPB, 1)
void ssd_fused_kernel(const float* __restrict__ logits,
                      const float* __restrict__ dbox,
                      float* __restrict__ out,
                      int B, int N)
{
    // Dynamic SMEM: per-warp staging buffer, 32 anchors * 25 floats = 800 floats/warp
    extern __shared__ float stage[];

    __shared__ float          s_sc[MAXN];     // effective scores (NEG for bg / invalid)
    __shared__ unsigned char  s_cl[MAXN];     // argmax class id
    __shared__ float          s_rv[WARPS];
    __shared__ int            s_ri[WARPS];
    __shared__ float          s_win[6];       // box(4), score
    __shared__ int            s_widx;

    const int b   = blockIdx.x;
    const int tid = threadIdx.x;
    const int w   = tid >> 5;
    const int l   = tid & 31;

    float* buf = stage + w * 800;
    const float* lg = logits + (size_t)b * (size_t)N * 25u;

    float4 boxv[ITEMS];   // decoded clipped boxes, register-resident

    // ---------------- Phase A: decode + softmax-max, staged through SMEM ----
    #pragma unroll
    for (int s = 0; s < ITEMS; ++s) {
        const int n0 = s * TPB + w * 32;         // first anchor of this warp's group
        int nv = N - n0; if (nv > 32) nv = 32;   // valid anchors in group

        if (nv == 32) {
            // 32 anchors * 25 floats = 800 floats = 200 float4, 16B-aligned
            const float4* g4 = reinterpret_cast<const float4*>(lg + (size_t)n0 * 25u);
            float4* b4 = reinterpret_cast<float4*>(buf);
            #pragma unroll
            for (int k = 0; k < 6; ++k) b4[l + 32 * k] = g4[l + 32 * k];
            if (l < 8) b4[l + 192] = g4[l + 192];
        } else if (nv > 0) {
            const int fl = nv * 25;
            const float* g = lg + (size_t)n0 * 25u;
            for (int f = l; f < fl; f += 32) buf[f] = g[f];
        }
        __syncwarp();

        const int n = n0 + l;
        float4 bx = make_float4(0.f, 0.f, 0.f, 0.f);
        float  sc = NEGV;
        int    cls = 0;

        if (n < N) {
            const float* p = buf + l * 25;       // stride 25 -> bank-conflict-free

            // argmax over class logits (== argmax of softmax), first-index tie-break
            float m = p[4];
            cls = 0;
            #pragma unroll
            for (int j = 1; j < 21; ++j) {
                float v = p[4 + j];
                if (v > m) { m = v; cls = j; }
            }
            // max softmax prob = 1 / sum(exp(l_j - m))
            float sum = 0.f;
            #pragma unroll
            for (int j = 0; j < 21; ++j) sum += __expf(p[4 + j] - m);
            const float prob = 1.0f / sum;

            // decode box
            const float4 db = reinterpret_cast<const float4*>(dbox)[n]; // [ymin,xmin,ymax,xmax]
            const float cy = 0.5f * (db.z + db.x);
            const float cx = 0.5f * (db.w + db.y);
            const float h  = db.z - db.x;
            const float wd = db.w - db.y;
            const float ncy = p[0] * h  + cy;
            const float ncx = p[1] * wd + cx;
            const float nh  = __expf(p[2]) * h;
            const float nw  = __expf(p[3]) * wd;
            bx.x = fminf(fmaxf(ncy - 0.5f * nh, 0.f), 1.f);
            bx.y = fminf(fmaxf(ncx - 0.5f * nw, 0.f), 1.f);
            bx.z = fminf(fmaxf(ncy + 0.5f * nh, 0.f), 1.f);
            bx.w = fminf(fmaxf(ncx + 0.5f * nw, 0.f), 1.f);

            sc = (cls != 0) ? prob : NEGV;   // background -> NEG exactly like ref
        }

        boxv[s] = bx;
        s_sc[s * TPB + tid] = sc;
        s_cl[s * TPB + tid] = (unsigned char)cls;
        __syncwarp();   // protect buf before next group's staging
    }

    __syncthreads();

    // ---------------- Phase B: greedy NMS, 5 iterations -----------------
    for (int it = 0; it < 5; ++it) {
        // local argmax (first-index on ties: ascending n, strict >)
        float bv = -3.0e38f;
        int   bi = 0x7fffffff;
        #pragma unroll
        for (int s = 0; s < ITEMS; ++s) {
            const int   n = s * TPB + tid;
            const float v = s_sc[n];
            if (v > bv) { bv = v; bi = n; }
        }
        // warp reduce with (max value, min index) tie-break
        #pragma unroll
        for (int off = 16; off; off >>= 1) {
            const float ov = __shfl_down_sync(0xffffffffu, bv, off);
            const int   oi = __shfl_down_sync(0xffffffffu, bi, off);
            if (ov > bv || (ov == bv && oi < bi)) { bv = ov; bi = oi; }
        }
        if (l == 0) { s_rv[w] = bv; s_ri[w] = bi; }
        __syncthreads();

        if (w == 0) {
            float rv = (l < WARPS) ? s_rv[l] : -3.0e38f;
            int   ri = (l < WARPS) ? s_ri[l] : 0x7fffffff;
            #pragma unroll
            for (int off = 8; off; off >>= 1) {
                const float ov = __shfl_down_sync(0xffffffffu, rv, off);
                const int   oi = __shfl_down_sync(0xffffffffu, ri, off);
                if (ov > rv || (ov == rv && oi < ri)) { rv = ov; ri = oi; }
            }
            if (l == 0) { s_widx = ri; s_win[4] = rv; }
        }
        __syncthreads();

        const int   widx = s_widx;
        const float wsc  = s_win[4];

        // owner thread publishes winner box (static-index select, no local spill)
        if (tid == (widx % TPB)) {
            const int slot = widx / TPB;
            float4 wb = make_float4(0.f, 0.f, 0.f, 0.f);
            #pragma unroll
            for (int s = 0; s < ITEMS; ++s) if (s == slot) wb = boxv[s];
            s_win[0] = wb.x; s_win[1] = wb.y; s_win[2] = wb.z; s_win[3] = wb.w;
        }
        __syncthreads();

        const float4 W = make_float4(s_win[0], s_win[1], s_win[2], s_win[3]);

        if (tid == 0) {
            const bool valid = wsc > 0.5f;     // CONFIDENCE_THRESHOLD
            float* o = out + ((size_t)b * 5 + it) * 6;
            o[0] = valid ? W.x : 0.f;
            o[1] = valid ? W.y : 0.f;
            o[2] = valid ? W.z : 0.f;
            o[3] = valid ? W.w : 0.f;
            o[4] = valid ? (float)s_cl[widx] : 0.f;
            o[5] = valid ? wsc : 0.f;
        }

        // suppression (suppresses winner too: IoU = 1 for non-degenerate boxes)
        const float aw = (W.z - W.x) * (W.w - W.y);
        #pragma unroll
        for (int s = 0; s < ITEMS; ++s) {
            const float4 bb = boxv[s];
            const float ty  = fmaxf(W.x, bb.x);
            const float tx  = fmaxf(W.y, bb.y);
            const float byc = fminf(W.z, bb.z);
            const float bxc = fminf(W.w, bb.w);
            const float ih  = fmaxf(byc - ty, 0.f);
            const float iw  = fmaxf(bxc - tx, 0.f);
            const float inter = ih * iw;
            const float ab  = (bb.z - bb.x) * (bb.w - bb.y);
            const float iou = inter / (aw + ab - inter + 1e-12f);
            if (iou > 0.5f) s_sc[s * TPB + tid] = NEGV;   // NMS_IOU_THRESHOLD
        }
        __syncthreads();
    }
}

extern "C" void kernel_launch(void* const* d_in, const int* in_sizes, int n_in,
                              void* d_out, int out_size)
{
    const float* logits = (const float*)d_in[0];   // [B, N, 25]
    const float* dbox   = (const float*)d_in[1];   // [N, 4]
    float* out          = (float*)d_out;           // [B, 5, 6]

    const int N = in_sizes[1] / 4;
    const int B = in_sizes[0] / (N * 25);

    const int dyn_smem = WARPS * 800 * (int)sizeof(float);  // 51200 B
    // Opt-in for >48KB total SMEM. Idempotent; safe if it no-ops during capture
    // since the attribute persists from the correctness run.
    cudaFuncSetAttribute(ssd_fused_kernel,
                         cudaFuncAttributeMaxDynamicSharedMemorySize, dyn_smem);

    ssd_fused_kernel<<<B, TPB, dyn_smem>>>(logits, dbox, out, B, N);
}

// round 3
// speedup vs baseline: 1.6888x; 1.6888x over previous
#include <cuda_runtime.h>
#include <cstdint>
#include <cstddef>

#define NEGV (-1e9f)

// ---------------- scratch (static __device__, no allocation) ----------------
constexpr int MAX_CAND = 1200000;   // >= B*N = 1,117,696
constexpr int MAX_B    = 256;

__device__ float4        g_box[MAX_CAND];
__device__ float         g_sc [MAX_CAND];
__device__ int           g_idx[MAX_CAND];
__device__ unsigned char g_cls[MAX_CAND];
__device__ int           g_cnt[MAX_B];

// ---------------- kernel 0: zero counters ----------------
__global__ void zero_cnt_kernel() {
    if (threadIdx.x < MAX_B) g_cnt[threadIdx.x] = 0;
}

// ---------------- kernel 1: decode + score + compact ----------------
// Grid-stride over 32-anchor groups. Each warp stages one group (3200 B) of
// logits into SMEM via coalesced float4, then each lane scores its anchor.
// Survivors (cls != 0, prob > 0.45, loose bound of the 0.5 threshold) are
// decoded and pushed to per-batch candidate lists.
constexpr int TPB1   = 256;
constexpr int WARPS1 = TPB1 / 32;

__global__ __launch_bounds__(TPB1)
void decode_kernel(const float* __restrict__ logits,
                   const float* __restrict__ dbox,
                   int B, int N)
{
    extern __shared__ float stage[];           // WARPS1 * 800 floats
    const int w = threadIdx.x >> 5;
    const int l = threadIdx.x & 31;
    float* buf = stage + w * 800;

    const int total  = B * N;
    const int groups = total >> 5;             // B*N divisible by 32 (guard below for tails)
    const int wg     = blockIdx.x * WARPS1 + w;
    const int wtot   = gridDim.x * WARPS1;

    for (int g = wg; g < groups; g += wtot) {
        const size_t a0 = (size_t)g << 5;

        // stage 32 anchors * 25 floats = 200 float4 (16B-aligned: a0*100 % 16 == 0)
        const float4* g4 = reinterpret_cast<const float4*>(logits + a0 * 25u);
        float4* b4 = reinterpret_cast<float4*>(buf);
        #pragma unroll
        for (int k = 0; k < 6; ++k) b4[l + 32 * k] = g4[l + 32 * k];
        if (l < 8) b4[l + 192] = g4[l + 192];
        __syncwarp();

        const int a = (int)a0 + l;             // global anchor id
        const int b = a / N;
        const int n = a - b * N;

        const float* p = buf + l * 25;         // stride 25 -> conflict-free

        // argmax class (first-index tie-break) + softmax denominator
        float m = p[4]; int cls = 0;
        #pragma unroll
        for (int j = 1; j < 21; ++j) {
            const float v = p[4 + j];
            if (v > m) { m = v; cls = j; }
        }
        float sum = 0.f;
        #pragma unroll
        for (int j = 0; j < 21; ++j) sum += __expf(p[4 + j] - m);
        const float prob = 1.0f / sum;

        // Loose filter: anything that could matter for output has prob > 0.5.
        // Extras in (0.45, 0.5] are harmless (proof: greedy picks are
        // non-increasing; a pick <= 0.5 and everything after it emits zeros).
        if (cls != 0 && prob > 0.45f) {
            const float4 db = reinterpret_cast<const float4*>(dbox)[n];
            const float cy = 0.5f * (db.z + db.x);
            const float cx = 0.5f * (db.w + db.y);
            const float h  = db.z - db.x;
            const float wd = db.w - db.y;
            const float ncy = p[0] * h  + cy;
            const float ncx = p[1] * wd + cx;
            const float nh  = __expf(p[2]) * h;
            const float nw  = __expf(p[3]) * wd;
            float4 bx;
            bx.x = fminf(fmaxf(ncy - 0.5f * nh, 0.f), 1.f);
            bx.y = fminf(fmaxf(ncx - 0.5f * nw, 0.f), 1.f);
            bx.z = fminf(fmaxf(ncy + 0.5f * nh, 0.f), 1.f);
            bx.w = fminf(fmaxf(ncx + 0.5f * nw, 0.f), 1.f);

            const int slot = atomicAdd(&g_cnt[b], 1);
            const size_t o = (size_t)b * (size_t)N + (size_t)slot;
            g_box[o] = bx;
            g_sc [o] = prob;
            g_idx[o] = n;
            g_cls[o] = (unsigned char)cls;
        }
        __syncwarp();                           // protect buf for next group
    }
}

// ---------------- kernel 2: per-batch greedy NMS over candidates ----------------
constexpr int TPB2   = 256;
constexpr int WARPS2 = TPB2 / 32;

__global__ __launch_bounds__(TPB2, 1)
void nms_kernel(float* __restrict__ out, int N)
{
    extern __shared__ char smraw[];
    float* sc  = reinterpret_cast<float*>(smraw);            // [N]
    int*   idx = reinterpret_cast<int*>(smraw + (size_t)N * 4); // [N]
    unsigned char* cl = reinterpret_cast<unsigned char*>(smraw + (size_t)N * 8); // [N]

    __shared__ float s_rv[WARPS2];
    __shared__ int   s_ri[WARPS2], s_rs[WARPS2];
    __shared__ float s_wbox[4];
    __shared__ float s_wsc;
    __shared__ int   s_wslot, s_wcls;

    const int b   = blockIdx.x;
    const int tid = threadIdx.x;
    const int w   = tid >> 5;
    const int l   = tid & 31;

    const size_t base = (size_t)b * (size_t)N;
    const int cnt = g_cnt[b];

    for (int i = tid; i < cnt; i += TPB2) {
        sc [i] = g_sc [base + i];
        idx[i] = g_idx[base + i];
        cl [i] = g_cls[base + i];
    }
    __syncthreads();

    for (int it = 0; it < 5; ++it) {
        // block argmax with (max score, min original-index) tie-break
        float bv = -3.0e38f; int bi = 0x7fffffff; int bs = -1;
        for (int i = tid; i < cnt; i += TPB2) {
            const float v = sc[i];
            const int   ix = idx[i];
            if (v > bv || (v == bv && ix < bi)) { bv = v; bi = ix; bs = i; }
        }
        #pragma unroll
        for (int off = 16; off; off >>= 1) {
            const float ov = __shfl_down_sync(0xffffffffu, bv, off);
            const int   oi = __shfl_down_sync(0xffffffffu, bi, off);
            const int   os = __shfl_down_sync(0xffffffffu, bs, off);
            if (ov > bv || (ov == bv && oi < bi)) { bv = ov; bi = oi; bs = os; }
        }
        if (l == 0) { s_rv[w] = bv; s_ri[w] = bi; s_rs[w] = bs; }
        __syncthreads();
        if (w == 0) {
            float rv = (l < WARPS2) ? s_rv[l] : -3.0e38f;
            int   ri = (l < WARPS2) ? s_ri[l] : 0x7fffffff;
            int   rs = (l < WARPS2) ? s_rs[l] : -1;
            #pragma unroll
            for (int off = 4; off; off >>= 1) {
                const float ov = __shfl_down_sync(0xffffffffu, rv, off);
                const int   oi = __shfl_down_sync(0xffffffffu, ri, off);
                const int   os = __shfl_down_sync(0xffffffffu, rs, off);
                if (ov > rv || (ov == rv && oi < ri)) { rv = ov; ri = oi; rs = os; }
            }
            if (l == 0) {
                s_wsc = rv; s_wslot = rs;
                if (rs >= 0) {
                    const float4 wb = g_box[base + rs];
                    s_wbox[0] = wb.x; s_wbox[1] = wb.y;
                    s_wbox[2] = wb.z; s_wbox[3] = wb.w;
                    s_wcls = cl[rs];
                } else {
                    s_wbox[0] = s_wbox[1] = s_wbox[2] = s_wbox[3] = 0.f;
                    s_wcls = 0;
                }
            }
        }
        __syncthreads();

        const float wsc = s_wsc;
        const float4 W = make_float4(s_wbox[0], s_wbox[1], s_wbox[2], s_wbox[3]);

        if (tid == 0) {
            const bool valid = wsc > 0.5f;      // CONFIDENCE_THRESHOLD (exact)
            float* o = out + ((size_t)b * 5 + it) * 6;
            o[0] = valid ? W.x : 0.f;
            o[1] = valid ? W.y : 0.f;
            o[2] = valid ? W.z : 0.f;
            o[3] = valid ? W.w : 0.f;
            o[4] = valid ? (float)s_wcls : 0.f;
            o[5] = valid ? wsc : 0.f;
        }

        // suppress (winner self-suppressed via IoU=1 unless degenerate — same as ref)
        if (s_wslot >= 0) {
            const float aw = (W.z - W.x) * (W.w - W.y);
            for (int i = tid; i < cnt; i += TPB2) {
                const float4 bb = g_box[base + i];
                const float ty  = fmaxf(W.x, bb.x);
                const float tx  = fmaxf(W.y, bb.y);
                const float byc = fminf(W.z, bb.z);
                const float bxc = fminf(W.w, bb.w);
                const float ih  = fmaxf(byc - ty, 0.f);
                const float iw  = fmaxf(bxc - tx, 0.f);
                const float inter = ih * iw;
                const float ab  = (bb.z - bb.x) * (bb.w - bb.y);
                const float iou = inter / (aw + ab - inter + 1e-12f);
                if (iou > 0.5f) sc[i] = NEGV;
            }
        }
        __syncthreads();
    }
}

// ---------------- launch ----------------
extern "C" void kernel_launch(void* const* d_in, const int* in_sizes, int n_in,
                              void* d_out, int out_size)
{
    const float* logits = (const float*)d_in[0];   // [B, N, 25]
    const float* dbox   = (const float*)d_in[1];   // [N, 4]
    float* out          = (float*)d_out;           // [B, 5, 6]

    const int N = in_sizes[1] / 4;
    const int B = in_sizes[0] / (N * 25);

    const int smem1 = WARPS1 * 800 * (int)sizeof(float);       // 25.6 KB
    const int smem2 = N * 9 + 16;                              // ~78.6 KB

    cudaFuncSetAttribute(decode_kernel,
                         cudaFuncAttributeMaxDynamicSharedMemorySize, smem1);
    cudaFuncSetAttribute(nms_kernel,
                         cudaFuncAttributeMaxDynamicSharedMemorySize, smem2);

    const int groups = (B * N) / 32;
    int blocks1 = (groups + 3 * WARPS1 - 1) / (3 * WARPS1);    // ~3 groups/warp
    if (blocks1 > 1480) blocks1 = 1480;
    if (blocks1 < 1) blocks1 = 1;

    zero_cnt_kernel<<<1, MAX_B>>>();
    decode_kernel<<<blocks1, TPB1, smem1>>>(logits, dbox, B, N);
    nms_kernel<<<B, TPB2, smem2>>>(out, N);
}

// round 6
// speedup vs baseline: 1.8075x; 1.0703x over previous
#include <cuda_runtime.h>
#include <cstdint>
#include <cstddef>

#define NEGV (-1e9f)

// ---------------- scratch (static __device__, zero-init at load) ----------------
constexpr int MAX_CAND = 1200000;   // >= B*N = 1,117,696
constexpr int MAX_B    = 256;

__device__ float4        g_box[MAX_CAND];
__device__ float         g_sc [MAX_CAND];
__device__ int           g_idx[MAX_CAND];
__device__ unsigned char g_cls[MAX_CAND];
__device__ int           g_cnt[MAX_B];       // zero at load; nms resets after use

// ---------------- cp.async helpers ----------------
__device__ __forceinline__ void cp_async16(uint32_t smem_dst, const void* gsrc) {
    asm volatile("cp.async.cg.shared.global [%0], [%1], 16;\n"
                 :: "r"(smem_dst), "l"(gsrc));
}
__device__ __forceinline__ void cp_commit() {
    asm volatile("cp.async.commit_group;\n");
}
template <int Nn>
__device__ __forceinline__ void cp_wait() {
    asm volatile("cp.async.wait_group %0;\n" :: "n"(Nn));
}

// ---------------- kernel 1: decode + score + compact (cp.async pipelined) ----
constexpr int TPB1   = 256;
constexpr int WARPS1 = TPB1 / 32;

// Per-warp double buffer: 2 x 800 floats (32 anchors * 25 floats)
__global__ __launch_bounds__(TPB1)
void decode_kernel(const float* __restrict__ logits,
                   const float* __restrict__ dbox,
                   int B, int N)
{
    extern __shared__ float stage[];           // WARPS1 * 1600 floats
    const int w = threadIdx.x >> 5;
    const int l = threadIdx.x & 31;

    float* buf0 = stage + w * 1600;
    float* buf1 = buf0 + 800;

    const int total  = B * N;
    const int groups = total >> 5;             // B*N divisible by 32
    const int wtot   = gridDim.x * WARPS1;
    const int wg     = blockIdx.x * WARPS1 + w;

    // issue one group's staging loads (this lane's share): 6 x 16B + tail
    auto issue = [&](float* dst, int g) {
        const float* src = logits + ((size_t)g << 5) * 25u;
        uint32_t sdst = (uint32_t)__cvta_generic_to_shared(dst);
        #pragma unroll
        for (int k = 0; k < 6; ++k)
            cp_async16(sdst + (uint32_t)(l + 32 * k) * 16u,
                       src + (size_t)(l + 32 * k) * 4u);
        if (l < 8)
            cp_async16(sdst + (uint32_t)(l + 192) * 16u,
                       src + (size_t)(l + 192) * 4u);
        cp_commit();
    };

    int g = wg;
    if (g < groups) issue(buf0, g);
    int pb = 0;

    for (; g < groups; g += wtot) {
        const int gn = g + wtot;
        float* cur = pb ? buf1 : buf0;
        float* nxt = pb ? buf0 : buf1;

        if (gn < groups) { issue(nxt, gn); cp_wait<1>(); }
        else             { cp_wait<0>(); }
        __syncwarp();

        const int a = (g << 5) + l;            // global anchor id
        const int b = a / N;
        const int n = a - b * N;

        const float* p = cur + l * 25;         // stride 25 -> conflict-free

        // argmax class (first-index tie-break) + softmax denominator
        float m = p[4]; int cls = 0;
        #pragma unroll
        for (int j = 1; j < 21; ++j) {
            const float v = p[4 + j];
            if (v > m) { m = v; cls = j; }
        }
        float sum = 0.f;
        #pragma unroll
        for (int j = 0; j < 21; ++j) sum += __expf(p[4 + j] - m);
        const float prob = 1.0f / sum;

        // Loose filter (margin below the 0.5 threshold): extras in (0.45, 0.5]
        // are provably harmless — greedy picks are non-increasing, and any pick
        // <= 0.5 (and everything after) emits zeros.
        if (cls != 0 && prob > 0.45f) {
            const float4 db = reinterpret_cast<const float4*>(dbox)[n];
            const float cy = 0.5f * (db.z + db.x);
            const float cx = 0.5f * (db.w + db.y);
            const float h  = db.z - db.x;
            const float wd = db.w - db.y;
            const float ncy = p[0] * h  + cy;
            const float ncx = p[1] * wd + cx;
            const float nh  = __expf(p[2]) * h;
            const float nw  = __expf(p[3]) * wd;
            float4 bx;
            bx.x = fminf(fmaxf(ncy - 0.5f * nh, 0.f), 1.f);
            bx.y = fminf(fmaxf(ncx - 0.5f * nw, 0.f), 1.f);
            bx.z = fminf(fmaxf(ncy + 0.5f * nh, 0.f), 1.f);
            bx.w = fminf(fmaxf(ncx + 0.5f * nw, 0.f), 1.f);

            const int slot = atomicAdd(&g_cnt[b], 1);
            const size_t o = (size_t)b * (size_t)N + (size_t)slot;
            g_box[o] = bx;
            g_sc [o] = prob;
            g_idx[o] = n;
            g_cls[o] = (unsigned char)cls;
        }
        __syncwarp();                           // buf reuse protection
        pb ^= 1;
    }
}

// ---------------- kernel 2: per-batch greedy NMS over candidates ----------------
constexpr int TPB2   = 256;
constexpr int WARPS2 = TPB2 / 32;

__global__ __launch_bounds__(TPB2, 1)
void nms_kernel(float* __restrict__ out, int N)
{
    extern __shared__ char smraw[];
    float* sc  = reinterpret_cast<float*>(smraw);                        // [N]
    int*   idx = reinterpret_cast<int*>(smraw + (size_t)N * 4);          // [N]
    unsigned char* cl = reinterpret_cast<unsigned char*>(smraw + (size_t)N * 8); // [N]

    __shared__ float s_rv[WARPS2];
    __shared__ int   s_ri[WARPS2], s_rs[WARPS2];
    __shared__ float s_wbox[4];
    __shared__ float s_wsc;
    __shared__ int   s_wslot, s_wcls;

    const int b   = blockIdx.x;
    const int tid = threadIdx.x;
    const int w   = tid >> 5;
    const int l   = tid & 31;

    const size_t base = (size_t)b * (size_t)N;
    const int cnt = g_cnt[b];

    for (int i = tid; i < cnt; i += TPB2) {
        sc [i] = g_sc [base + i];
        idx[i] = g_idx[base + i];
        cl [i] = g_cls[base + i];
    }
    __syncthreads();

    for (int it = 0; it < 5; ++it) {
        // block argmax with (max score, min original-anchor-index) tie-break
        float bv = -3.0e38f; int bi = 0x7fffffff; int bs = -1;
        for (int i = tid; i < cnt; i += TPB2) {
            const float v  = sc[i];
            const int   ix = idx[i];
            if (v > bv || (v == bv && ix < bi)) { bv = v; bi = ix; bs = i; }
        }
        #pragma unroll
        for (int off = 16; off; off >>= 1) {
            const float ov = __shfl_down_sync(0xffffffffu, bv, off);
            const int   oi = __shfl_down_sync(0xffffffffu, bi, off);
            const int   os = __shfl_down_sync(0xffffffffu, bs, off);
            if (ov > bv || (ov == bv && oi < bi)) { bv = ov; bi = oi; bs = os; }
        }
        if (l == 0) { s_rv[w] = bv; s_ri[w] = bi; s_rs[w] = bs; }
        __syncthreads();
        if (w == 0) {
            float rv = (l < WARPS2) ? s_rv[l] : -3.0e38f;
            int   ri = (l < WARPS2) ? s_ri[l] : 0x7fffffff;
            int   rs = (l < WARPS2) ? s_rs[l] : -1;
            #pragma unroll
            for (int off = 4; off; off >>= 1) {
                const float ov = __shfl_down_sync(0xffffffffu, rv, off);
                const int   oi = __shfl_down_sync(0xffffffffu, ri, off);
                const int   os = __shfl_down_sync(0xffffffffu, rs, off);
                if (ov > rv || (ov == rv && oi < ri)) { rv = ov; ri = oi; rs = os; }
            }
            if (l == 0) {
                s_wsc = rv; s_wslot = rs;
                if (rs >= 0) {
                    const float4 wb = g_box[base + rs];
                    s_wbox[0] = wb.x; s_wbox[1] = wb.y;
                    s_wbox[2] = wb.z; s_wbox[3] = wb.w;
                    s_wcls = cl[rs];
                } else {
                    s_wbox[0] = s_wbox[1] = s_wbox[2] = s_wbox[3] = 0.f;
                    s_wcls = 0;
                }
            }
        }
        __syncthreads();

        const float wsc = s_wsc;
        const float4 W = make_float4(s_wbox[0], s_wbox[1], s_wbox[2], s_wbox[3]);

        if (tid == 0) {
            const bool valid = wsc > 0.5f;      // CONFIDENCE_THRESHOLD (exact)
            float* o = out + ((size_t)b * 5 + it) * 6;
            o[0] = valid ? W.x : 0.f;
            o[1] = valid ? W.y : 0.f;
            o[2] = valid ? W.z : 0.f;
            o[3] = valid ? W.w : 0.f;
            o[4] = valid ? (float)s_wcls : 0.f;
            o[5] = valid ? wsc : 0.f;
        }

        // suppress (winner self-suppressed via IoU=1 unless degenerate — same as ref)
        if (s_wslot >= 0) {
            const float aw = (W.z - W.x) * (W.w - W.y);
            for (int i = tid; i < cnt; i += TPB2) {
                const float4 bb = g_box[base + i];
                const float ty  = fmaxf(W.x, bb.x);
                const float tx  = fmaxf(W.y, bb.y);
                const float byc = fminf(W.z, bb.z);
                const float bxc = fminf(W.w, bb.w);
                const float ih  = fmaxf(byc - ty, 0.f);
                const float iw  = fmaxf(bxc - tx, 0.f);
                const float inter = ih * iw;
                const float ab  = (bb.z - bb.x) * (bb.w - bb.y);
                const float iou = inter / (aw + ab - inter + 1e-12f);
                if (iou > 0.5f) sc[i] = NEGV;
            }
        }
        __syncthreads();
    }

    // reset counter for the next graph replay (deterministic: count was
    // consumed above; first launch sees the load-time zero-init).
    if (tid == 0) g_cnt[b] = 0;
}

// ---------------- launch ----------------
extern "C" void kernel_launch(void* const* d_in, const int* in_sizes, int n_in,
                              void* d_out, int out_size)
{
    const float* logits = (const float*)d_in[0];   // [B, N, 25]
    const float* dbox   = (const float*)d_in[1];   // [N, 4]
    float* out          = (float*)d_out;           // [B, 5, 6]

    const int N = in_sizes[1] / 4;
    const int B = in_sizes[0] / (N * 25);

    const int smem1 = WARPS1 * 1600 * (int)sizeof(float);      // 51.2 KB
    const int smem2 = N * 9 + 16;                              // ~78.6 KB

    cudaFuncSetAttribute(decode_kernel,
                         cudaFuncAttributeMaxDynamicSharedMemorySize, smem1);
    cudaFuncSetAttribute(nms_kernel,
                         cudaFuncAttributeMaxDynamicSharedMemorySize, smem2);

    const int groups = (B * N) / 32;
    int blocks1 = (groups + 3 * WARPS1 - 1) / (3 * WARPS1);    // ~3 groups/warp
    if (blocks1 > 1480) blocks1 = 1480;
    if (blocks1 < 1) blocks1 = 1;

    decode_kernel<<<blocks1, TPB1, smem1>>>(logits, dbox, B, N);
    nms_kernel<<<B, TPB2, smem2>>>(out, N);
}